// round 1
// baseline (speedup 1.0000x reference)
#include <cuda_runtime.h>
#include <cstdint>

#define BB 4
#define CC 512
#define KK 64
#define NN 1024
#define CT 16

// ---- scratch (static __device__, no allocations) ----
__device__ float g_inv[KK * CC];    // [k][c]  1/(sigma+1e-7)
__device__ float g_inv2t[CC * KK];  // [c][k]  inv^2
__device__ float g_m2t[CC * KK];    // [c][k]  -2*anchor*inv^2
__device__ float g_ck[KK];          // sum_c anchor^2*inv^2
__device__ float g_wpart[(NN / 32) * BB * KK];  // per-n-tile wsum partials
__device__ float g_part[4 * BB * KK * CC];      // split-N partials of num
__device__ float g_rc[BB * KK];                 // per-row flat-norm contribution

// ------------------------------------------------------------------
// Kernel 1: precompute per-(k,c) quantities + per-k constant
// ------------------------------------------------------------------
__global__ __launch_bounds__(256) void k1_prep(const float* __restrict__ anchor,
                                               const float* __restrict__ sp) {
    const int k = blockIdx.x;
    const int tid = threadIdx.x;
    float cks = 0.f;
#pragma unroll
    for (int r = 0; r < CC / 256; r++) {
        const int c = tid + r * 256;
        const float s = 1.f / (1.f + expf(-sp[k * CC + c]));
        const float inv = 1.f / (s + 1e-7f);
        const float inv2 = inv * inv;
        const float a = anchor[k * CC + c];
        g_inv[k * CC + c] = inv;
        g_inv2t[c * KK + k] = inv2;
        g_m2t[c * KK + k] = -2.f * a * inv2;
        cks += a * a * inv2;
    }
    __shared__ float red[256];
    red[tid] = cks;
    __syncthreads();
    for (int s = 128; s > 0; s >>= 1) {
        if (tid < s) red[tid] += red[tid + s];
        __syncthreads();
    }
    if (tid == 0) g_ck[k] = red[0];
}

// ------------------------------------------------------------------
// Kernel 2: d2 GEMM (K=64 x n-tile=32, inner C=512) + fused softmax over K
// grid (NN/32, BB), 256 threads. Each thread: 4k x 2n accumulators.
// ------------------------------------------------------------------
__global__ __launch_bounds__(256) void k2_d2_softmax(const float* __restrict__ x,
                                                     float* __restrict__ soft_out) {
    const int b = blockIdx.y;
    const int nb = blockIdx.x;
    const int n0 = nb * 32;

    __shared__ float Wis[CT * 64];
    __shared__ float M2s[CT * 64];
    __shared__ float Xs[CT * 32];
    __shared__ float S[64 * 33];

    const int tid = threadIdx.x;
    const int tn = tid & 15;   // n pair index
    const int tk = tid >> 4;   // k quad index

    float acc[4][2];
#pragma unroll
    for (int i = 0; i < 4; i++) { acc[i][0] = 0.f; acc[i][1] = 0.f; }

    const float* xb = x + (size_t)b * CC * NN;

    for (int c0 = 0; c0 < CC; c0 += CT) {
#pragma unroll
        for (int r = 0; r < 4; r++) {
            const int idx = tid + r * 256;          // 0..1023
            const int cc = idx >> 6, kk = idx & 63;
            Wis[idx] = g_inv2t[(c0 + cc) * KK + kk];
            M2s[idx] = g_m2t[(c0 + cc) * KK + kk];
        }
#pragma unroll
        for (int r = 0; r < 2; r++) {
            const int idx = tid + r * 256;          // 0..511
            const int cc = idx >> 5, nn = idx & 31;
            Xs[idx] = xb[(size_t)(c0 + cc) * NN + n0 + nn];
        }
        __syncthreads();
#pragma unroll
        for (int cc = 0; cc < CT; cc++) {
            const float xv0 = Xs[cc * 32 + tn * 2];
            const float xv1 = Xs[cc * 32 + tn * 2 + 1];
#pragma unroll
            for (int i = 0; i < 4; i++) {
                const float w1 = Wis[cc * 64 + tk * 4 + i];
                const float m2 = M2s[cc * 64 + tk * 4 + i];
                const float t0 = fmaf(w1, xv0, m2);
                const float t1 = fmaf(w1, xv1, m2);
                acc[i][0] = fmaf(t0, xv0, acc[i][0]);
                acc[i][1] = fmaf(t1, xv1, acc[i][1]);
            }
        }
        __syncthreads();
    }

    // logits -> shared (pad 33 for conflict-free column reads)
#pragma unroll
    for (int i = 0; i < 4; i++) {
        const int k = tk * 4 + i;
        const float ck = g_ck[k];
        S[k * 33 + tn * 2]     = -0.5f * (acc[i][0] + ck);
        S[k * 33 + tn * 2 + 1] = -0.5f * (acc[i][1] + ck);
    }
    __syncthreads();

    // softmax over K per column (threads 0..31)
    if (tid < 32) {
        const int n = tid;
        float m = -1e30f;
#pragma unroll
        for (int k = 0; k < KK; k++) m = fmaxf(m, S[k * 33 + n]);
        float s = 0.f;
#pragma unroll
        for (int k = 0; k < KK; k++) s += expf(S[k * 33 + n] - m);
        const float invs = 1.f / s;
        float* outp = soft_out + (size_t)b * KK * NN + n0 + n;
#pragma unroll
        for (int k = 0; k < KK; k++) {
            const float p = expf(S[k * 33 + n] - m) * invs;
            S[k * 33 + n] = p;
            outp[(size_t)k * NN] = p;
        }
    }
    __syncthreads();

    // deterministic per-block wsum partial (threads 0..63, one per k)
    if (tid < 64) {
        const int k = tid;
        float s = 0.f;
#pragma unroll
        for (int n = 0; n < 32; n++) s += S[k * 33 + n];
        g_wpart[(nb * BB + b) * KK + k] = s;
    }
}

// ------------------------------------------------------------------
// Kernel 3: num[b,k,c] = sum_n A[b,k,n]*x[b,c,n], split-N=4 partials
// grid (CC/64, BB, 4), 256 threads, 64x64 tile, inner n chunk = 16
// ------------------------------------------------------------------
__global__ __launch_bounds__(256) void k3_num(const float* __restrict__ soft,
                                              const float* __restrict__ x) {
    const int b = blockIdx.y;
    const int c0 = blockIdx.x * 64;
    const int ns = blockIdx.z;
    const int nbeg = ns * (NN / 4);

    __shared__ float As[16 * 65];
    __shared__ float Xs[16 * 65];

    const int tid = threadIdx.x;
    const int tc = tid & 15;
    const int tk = tid >> 4;

    float acc[4][4];
#pragma unroll
    for (int i = 0; i < 4; i++)
#pragma unroll
        for (int j = 0; j < 4; j++) acc[i][j] = 0.f;

    const float* Ab = soft + (size_t)b * KK * NN;
    const float* xb = x + (size_t)b * CC * NN;

    for (int n0 = nbeg; n0 < nbeg + NN / 4; n0 += 16) {
#pragma unroll
        for (int r = 0; r < 4; r++) {
            const int idx = tid + r * 256;   // 0..1023
            const int row = idx >> 4;        // 0..63 (k or c-local)
            const int nn = idx & 15;
            As[nn * 65 + row] = Ab[(size_t)row * NN + n0 + nn];
            Xs[nn * 65 + row] = xb[(size_t)(c0 + row) * NN + n0 + nn];
        }
        __syncthreads();
#pragma unroll
        for (int nn = 0; nn < 16; nn++) {
            float a4[4], x4[4];
#pragma unroll
            for (int i = 0; i < 4; i++) a4[i] = As[nn * 65 + tk * 4 + i];
#pragma unroll
            for (int j = 0; j < 4; j++) x4[j] = Xs[nn * 65 + tc * 4 + j];
#pragma unroll
            for (int i = 0; i < 4; i++)
#pragma unroll
                for (int j = 0; j < 4; j++)
                    acc[i][j] = fmaf(a4[i], x4[j], acc[i][j]);
        }
        __syncthreads();
    }

    float* P = g_part + ((size_t)ns * BB + b) * KK * CC;
#pragma unroll
    for (int i = 0; i < 4; i++)
#pragma unroll
        for (int j = 0; j < 4; j++)
            P[(size_t)(tk * 4 + i) * CC + c0 + tc * 4 + j] = acc[i][j];
}

// ------------------------------------------------------------------
// Kernel 4: epilogue per (b,k): combine partials, subtract, scale, row-normalize
// grid (KK, BB), 256 threads (2 c each)
// ------------------------------------------------------------------
__global__ __launch_bounds__(256) void k4_nodes(const float* __restrict__ anchor,
                                                float* __restrict__ nodes_out) {
    const int k = blockIdx.x;
    const int b = blockIdx.y;
    const int tid = threadIdx.x;

    __shared__ float wsh;
    if (tid == 0) {
        float w = 0.f;
#pragma unroll
        for (int i = 0; i < NN / 32; i++) w += g_wpart[(i * BB + b) * KK + k];
        wsh = w;
    }
    __syncthreads();
    const float w = wsh;
    const float invden = 1.f / (w + 1e-7f);

    float v[2];
    float ss = 0.f;
#pragma unroll
    for (int r = 0; r < 2; r++) {
        const int c = tid + r * 256;
        float num = 0.f;
#pragma unroll
        for (int ns = 0; ns < 4; ns++)
            num += g_part[((size_t)ns * BB + b) * KK * CC + (size_t)k * CC + c];
        const float val = (num - w * anchor[k * CC + c]) * g_inv[k * CC + c] * invden;
        v[r] = val;
        ss += val * val;
    }

    __shared__ float red[256];
    red[tid] = ss;
    __syncthreads();
    for (int s = 128; s > 0; s >>= 1) {
        if (tid < s) red[tid] += red[tid + s];
        __syncthreads();
    }
    const float sumsq = red[0];
    const float rn = sqrtf(sumsq);
    const float rf = 1.f / fmaxf(rn, 1e-12f);
    if (tid == 0) g_rc[b * KK + k] = sumsq * rf * rf;   // ||row||^2 after normalize

#pragma unroll
    for (int r = 0; r < 2; r++) {
        const int c = tid + r * 256;
        nodes_out[((size_t)b * KK + k) * CC + c] = v[r] * rf;
    }
}

// ------------------------------------------------------------------
// Kernel 5: flat normalization per batch (deterministic tree reduce over k)
// ------------------------------------------------------------------
__global__ __launch_bounds__(256) void k5_scale(float* __restrict__ nodes_out) {
    const int b = blockIdx.x;
    const int tid = threadIdx.x;
    __shared__ float red[64];
    if (tid < 64) red[tid] = g_rc[b * KK + tid];
    __syncthreads();
    for (int s = 32; s > 0; s >>= 1) {
        if (tid < s) red[tid] += red[tid + s];
        __syncthreads();
    }
    const float f = 1.f / fmaxf(sqrtf(red[0]), 1e-12f);
    float* p = nodes_out + (size_t)b * KK * CC;
    for (int i = tid; i < KK * CC; i += blockDim.x) p[i] *= f;
}

// ------------------------------------------------------------------
extern "C" void kernel_launch(void* const* d_in, const int* in_sizes, int n_in,
                              void* d_out, int out_size) {
    (void)in_sizes; (void)n_in; (void)out_size;
    const float* x = (const float*)d_in[0];       // (B, C, H, W) = (4,512,32,32)
    const float* anchor = (const float*)d_in[1];  // (K, C)
    const float* sp = (const float*)d_in[2];      // (K, C) pre-sigmoid
    float* out = (float*)d_out;
    float* nodes_out = out;                          // B*K*C (viewed (B,C,K))
    float* soft_out = out + (size_t)BB * KK * CC;    // B*K*N

    k1_prep<<<KK, 256>>>(anchor, sp);
    dim3 g2(NN / 32, BB);
    k2_d2_softmax<<<g2, 256>>>(x, soft_out);
    dim3 g3(CC / 64, BB, 4);
    k3_num<<<g3, 256>>>(soft_out, x);
    dim3 g4(KK, BB);
    k4_nodes<<<g4, 256>>>(anchor, nodes_out);
    k5_scale<<<BB, 256>>>(nodes_out);
}

// round 2
// speedup vs baseline: 1.9993x; 1.9993x over previous
#include <cuda_runtime.h>
#include <cstdint>

#define BB 4
#define CC 512
#define KK 64
#define NN 1024

typedef unsigned long long ull;

// ---- scratch (static __device__, no allocations) ----
__device__ __align__(16) float g_inv[KK * CC];    // [k][c]  1/(sigma+1e-7)
__device__ __align__(16) float g_inv2t[CC * KK];  // [c][k]  inv^2
__device__ __align__(16) float g_m2t[CC * KK];    // [c][k]  -2*anchor*inv^2
__device__ __align__(16) float g_ck[KK];          // sum_c anchor^2*inv^2
__device__ __align__(16) float g_wpart[(NN / 32) * BB * KK];  // per-n-tile wsum partials
__device__ __align__(16) float g_part[4 * BB * KK * CC];      // split-N partials of num
__device__ __align__(16) float g_rc[BB * KK];                 // per-row flat-norm contribution

// ---- f32x2 helpers (sm_100+ packed fp32 FMA) ----
__device__ __forceinline__ ull pack2(float x, float y) {
    ull r; asm("mov.b64 %0, {%1,%2};" : "=l"(r) : "f"(x), "f"(y)); return r;
}
__device__ __forceinline__ ull fma2(ull a, ull b, ull c) {
    ull d; asm("fma.rn.f32x2 %0, %1, %2, %3;" : "=l"(d) : "l"(a), "l"(b), "l"(c)); return d;
}
__device__ __forceinline__ float2 unpack2(ull v) {
    float2 f; asm("mov.b64 {%0,%1}, %2;" : "=f"(f.x), "=f"(f.y) : "l"(v)); return f;
}

// ---- cp.async helpers ----
__device__ __forceinline__ void cp_async16(void* smem_dst, const void* gsrc) {
    unsigned sa = (unsigned)__cvta_generic_to_shared(smem_dst);
    asm volatile("cp.async.cg.shared.global [%0], [%1], 16;\n" :: "r"(sa), "l"(gsrc));
}
__device__ __forceinline__ void cp_commit() { asm volatile("cp.async.commit_group;\n"); }
template <int N>
__device__ __forceinline__ void cp_wait() { asm volatile("cp.async.wait_group %0;\n" :: "n"(N)); }

// ------------------------------------------------------------------
// Kernel 1: precompute per-(k,c) quantities + per-k constant
// ------------------------------------------------------------------
__global__ __launch_bounds__(256) void k1_prep(const float* __restrict__ anchor,
                                               const float* __restrict__ sp) {
    const int k = blockIdx.x;
    const int tid = threadIdx.x;
    float cks = 0.f;
#pragma unroll
    for (int r = 0; r < CC / 256; r++) {
        const int c = tid + r * 256;
        const float s = 1.f / (1.f + expf(-sp[k * CC + c]));
        const float inv = 1.f / (s + 1e-7f);
        const float inv2 = inv * inv;
        const float a = anchor[k * CC + c];
        g_inv[k * CC + c] = inv;
        g_inv2t[c * KK + k] = inv2;
        g_m2t[c * KK + k] = -2.f * a * inv2;
        cks += a * a * inv2;
    }
    __shared__ float red[256];
    red[tid] = cks;
    __syncthreads();
    for (int s = 128; s > 0; s >>= 1) {
        if (tid < s) red[tid] += red[tid + s];
        __syncthreads();
    }
    if (tid == 0) g_ck[k] = red[0];
}

// ------------------------------------------------------------------
// Kernel 2: d2 GEMM (64k x 32n, inner C=512) + fused softmax over K
// 128 threads, grid (NN/32, BB). Per thread 4k x 4n via f32x2 (k-pairs).
// cp.async double-buffered c-chunks of 16.
// ------------------------------------------------------------------
__global__ __launch_bounds__(128) void k2_d2_softmax(const float* __restrict__ x,
                                                     float* __restrict__ soft_out) {
    const int b = blockIdx.y;
    const int nb = blockIdx.x;
    const int n0 = nb * 32;
    const int tid = threadIdx.x;
    const int tk = tid >> 3;  // 0..15 -> k base = tk*4
    const int tn = tid & 7;   // 0..7  -> n base = tn*4

    __shared__ __align__(16) float Wis[2][16 * 64];
    __shared__ __align__(16) float M2s[2][16 * 64];
    __shared__ __align__(16) float Xs[2][16 * 32];
    __shared__ float S[64 * 33];

    const float* xb = x + (size_t)b * CC * NN;

    // issue loads for chunk into buffer buf
    auto issue = [&](int chunk, int buf) {
        const int c0 = chunk * 16;
#pragma unroll
        for (int r = 0; r < 2; r++) {
            const int idx = tid + r * 128;  // float4 index 0..255
            cp_async16(&Wis[buf][idx * 4], g_inv2t + c0 * KK + idx * 4);
            cp_async16(&M2s[buf][idx * 4], g_m2t + c0 * KK + idx * 4);
        }
        {
            const int cc = tid >> 3, nn4 = (tid & 7) * 4;  // 128 float4
            cp_async16(&Xs[buf][cc * 32 + nn4], xb + (size_t)(c0 + cc) * NN + n0 + nn4);
        }
        cp_commit();
    };

    ull acc[2][4];
#pragma unroll
    for (int i = 0; i < 2; i++)
#pragma unroll
        for (int j = 0; j < 4; j++) acc[i][j] = 0ull;

    issue(0, 0);
    for (int ch = 0; ch < 32; ch++) {
        if (ch + 1 < 32) { issue(ch + 1, (ch + 1) & 1); cp_wait<1>(); }
        else             { cp_wait<0>(); }
        __syncthreads();
        const float* Wb = Wis[ch & 1];
        const float* Mb = M2s[ch & 1];
        const float* Xb = Xs[ch & 1];
#pragma unroll
        for (int cc = 0; cc < 16; cc++) {
            const ulonglong2 wp = *reinterpret_cast<const ulonglong2*>(Wb + cc * 64 + tk * 4);
            const ulonglong2 mp = *reinterpret_cast<const ulonglong2*>(Mb + cc * 64 + tk * 4);
            const float4 xv = *reinterpret_cast<const float4*>(Xb + cc * 32 + tn * 4);
            const ull xd0 = pack2(xv.x, xv.x);
            const ull xd1 = pack2(xv.y, xv.y);
            const ull xd2 = pack2(xv.z, xv.z);
            const ull xd3 = pack2(xv.w, xv.w);
            ull t;
            t = fma2(wp.x, xd0, mp.x); acc[0][0] = fma2(t, xd0, acc[0][0]);
            t = fma2(wp.x, xd1, mp.x); acc[0][1] = fma2(t, xd1, acc[0][1]);
            t = fma2(wp.x, xd2, mp.x); acc[0][2] = fma2(t, xd2, acc[0][2]);
            t = fma2(wp.x, xd3, mp.x); acc[0][3] = fma2(t, xd3, acc[0][3]);
            t = fma2(wp.y, xd0, mp.y); acc[1][0] = fma2(t, xd0, acc[1][0]);
            t = fma2(wp.y, xd1, mp.y); acc[1][1] = fma2(t, xd1, acc[1][1]);
            t = fma2(wp.y, xd2, mp.y); acc[1][2] = fma2(t, xd2, acc[1][2]);
            t = fma2(wp.y, xd3, mp.y); acc[1][3] = fma2(t, xd3, acc[1][3]);
        }
        __syncthreads();
    }

    // logits -> shared (pad 33)
#pragma unroll
    for (int kp = 0; kp < 2; kp++)
#pragma unroll
        for (int j = 0; j < 4; j++) {
            const float2 v = unpack2(acc[kp][j]);
            const int k0 = tk * 4 + kp * 2;
            const int n = tn * 4 + j;
            S[k0 * 33 + n] = -0.5f * (v.x + g_ck[k0]);
            S[(k0 + 1) * 33 + n] = -0.5f * (v.y + g_ck[k0 + 1]);
        }
    __syncthreads();

    // softmax over K per column
    if (tid < 32) {
        const int n = tid;
        float m = -1e30f;
#pragma unroll
        for (int k = 0; k < KK; k++) m = fmaxf(m, S[k * 33 + n]);
        float s = 0.f;
#pragma unroll
        for (int k = 0; k < KK; k++) s += __expf(S[k * 33 + n] - m);
        const float invs = 1.f / s;
        float* outp = soft_out + (size_t)b * KK * NN + n0 + n;
#pragma unroll
        for (int k = 0; k < KK; k++) {
            const float p = __expf(S[k * 33 + n] - m) * invs;
            S[k * 33 + n] = p;
            outp[(size_t)k * NN] = p;
        }
    }
    __syncthreads();

    // deterministic per-block wsum partial
    if (tid < 64) {
        const int k = tid;
        float s = 0.f;
#pragma unroll
        for (int n = 0; n < 32; n++) s += S[k * 33 + n];
        g_wpart[(nb * BB + b) * KK + k] = s;
    }
}

// ------------------------------------------------------------------
// Kernel 3: num[b,k,c] = sum_n A[b,k,n]*x[b,c,n], split-N=4 partials
// grid (CC/64, BB, 4), 256 threads, 64x64 tile, f32x2 over c-pairs
// ------------------------------------------------------------------
__global__ __launch_bounds__(256) void k3_num(const float* __restrict__ soft,
                                              const float* __restrict__ x) {
    const int b = blockIdx.y;
    const int c0 = blockIdx.x * 64;
    const int ns = blockIdx.z;
    const int nbeg = ns * (NN / 4);

    __shared__ __align__(16) float As[16 * 66];
    __shared__ __align__(16) float Xs[16 * 66];

    const int tid = threadIdx.x;
    const int tc = tid & 15;
    const int tk = tid >> 4;

    ull acc2[4][2];
#pragma unroll
    for (int i = 0; i < 4; i++) { acc2[i][0] = 0ull; acc2[i][1] = 0ull; }

    const float* Ab = soft + (size_t)b * KK * NN;
    const float* xb = x + (size_t)b * CC * NN;

    for (int n0 = nbeg; n0 < nbeg + NN / 4; n0 += 16) {
#pragma unroll
        for (int r = 0; r < 4; r++) {
            const int idx = tid + r * 256;  // 0..1023
            const int row = idx >> 4;       // 0..63
            const int nn = idx & 15;
            As[nn * 66 + row] = Ab[(size_t)row * NN + n0 + nn];
            Xs[nn * 66 + row] = xb[(size_t)(c0 + row) * NN + n0 + nn];
        }
        __syncthreads();
#pragma unroll
        for (int nn = 0; nn < 16; nn++) {
            const float a0 = As[nn * 66 + tk * 4 + 0];
            const float a1 = As[nn * 66 + tk * 4 + 1];
            const float a2 = As[nn * 66 + tk * 4 + 2];
            const float a3 = As[nn * 66 + tk * 4 + 3];
            const ull ad0 = pack2(a0, a0);
            const ull ad1 = pack2(a1, a1);
            const ull ad2 = pack2(a2, a2);
            const ull ad3 = pack2(a3, a3);
            const ull xq0 = *reinterpret_cast<const ull*>(&Xs[nn * 66 + tc * 4]);
            const ull xq1 = *reinterpret_cast<const ull*>(&Xs[nn * 66 + tc * 4 + 2]);
            acc2[0][0] = fma2(ad0, xq0, acc2[0][0]);
            acc2[0][1] = fma2(ad0, xq1, acc2[0][1]);
            acc2[1][0] = fma2(ad1, xq0, acc2[1][0]);
            acc2[1][1] = fma2(ad1, xq1, acc2[1][1]);
            acc2[2][0] = fma2(ad2, xq0, acc2[2][0]);
            acc2[2][1] = fma2(ad2, xq1, acc2[2][1]);
            acc2[3][0] = fma2(ad3, xq0, acc2[3][0]);
            acc2[3][1] = fma2(ad3, xq1, acc2[3][1]);
        }
        __syncthreads();
    }

    float* P = g_part + ((size_t)ns * BB + b) * KK * CC;
#pragma unroll
    for (int i = 0; i < 4; i++)
#pragma unroll
        for (int jp = 0; jp < 2; jp++) {
            const float2 v = unpack2(acc2[i][jp]);
            *reinterpret_cast<float2*>(&P[(size_t)(tk * 4 + i) * CC + c0 + tc * 4 + jp * 2]) = v;
        }
}

// ------------------------------------------------------------------
// Kernel 4: epilogue per (b,k): combine partials, subtract, scale, row-normalize
// grid (KK, BB), 128 threads, float4 per thread
// ------------------------------------------------------------------
__global__ __launch_bounds__(128) void k4_nodes(const float* __restrict__ anchor,
                                                float* __restrict__ nodes_out) {
    const int k = blockIdx.x;
    const int b = blockIdx.y;
    const int tid = threadIdx.x;

    __shared__ float wsh;
    __shared__ float red[4];
    __shared__ float rfs;

    if (tid < 32) {
        float w = g_wpart[(tid * BB + b) * KK + k];
#pragma unroll
        for (int o = 16; o > 0; o >>= 1) w += __shfl_xor_sync(0xffffffffu, w, o);
        if (tid == 0) wsh = w;
    }
    __syncthreads();
    const float w = wsh;
    const float invden = 1.f / (w + 1e-7f);

    const int c = tid * 4;
    float4 s = make_float4(0.f, 0.f, 0.f, 0.f);
#pragma unroll
    for (int ns = 0; ns < 4; ns++) {
        const float4 p = *reinterpret_cast<const float4*>(
            &g_part[((size_t)ns * BB + b) * KK * CC + (size_t)k * CC + c]);
        s.x += p.x; s.y += p.y; s.z += p.z; s.w += p.w;
    }
    const float4 a = *reinterpret_cast<const float4*>(&anchor[k * CC + c]);
    const float4 iv = *reinterpret_cast<const float4*>(&g_inv[k * CC + c]);
    float4 v;
    v.x = (s.x - w * a.x) * iv.x * invden;
    v.y = (s.y - w * a.y) * iv.y * invden;
    v.z = (s.z - w * a.z) * iv.z * invden;
    v.w = (s.w - w * a.w) * iv.w * invden;

    float ss = v.x * v.x + v.y * v.y + v.z * v.z + v.w * v.w;
#pragma unroll
    for (int o = 16; o > 0; o >>= 1) ss += __shfl_xor_sync(0xffffffffu, ss, o);
    if ((tid & 31) == 0) red[tid >> 5] = ss;
    __syncthreads();
    if (tid == 0) {
        const float sumsq = red[0] + red[1] + red[2] + red[3];
        const float rn = sqrtf(sumsq);
        const float rf = 1.f / fmaxf(rn, 1e-12f);
        g_rc[b * KK + k] = sumsq * rf * rf;
        rfs = rf;
    }
    __syncthreads();
    const float rf = rfs;
    float4 o4;
    o4.x = v.x * rf; o4.y = v.y * rf; o4.z = v.z * rf; o4.w = v.w * rf;
    *reinterpret_cast<float4*>(&nodes_out[((size_t)b * KK + k) * CC + c]) = o4;
}

// ------------------------------------------------------------------
// Kernel 5: flat normalization, grid (KK, BB), 128 threads
// ------------------------------------------------------------------
__global__ __launch_bounds__(128) void k5_scale(float* __restrict__ nodes_out) {
    const int k = blockIdx.x;
    const int b = blockIdx.y;
    const int tid = threadIdx.x;
    __shared__ float red[2];
    __shared__ float fsh;
    if (tid < 64) {
        float v = g_rc[b * KK + tid];
#pragma unroll
        for (int o = 16; o > 0; o >>= 1) v += __shfl_xor_sync(0xffffffffu, v, o);
        if ((tid & 31) == 0) red[tid >> 5] = v;
    }
    __syncthreads();
    if (tid == 0) fsh = 1.f / fmaxf(sqrtf(red[0] + red[1]), 1e-12f);
    __syncthreads();
    const float f = fsh;
    const int c = tid * 4;
    float4* p = reinterpret_cast<float4*>(&nodes_out[((size_t)b * KK + k) * CC + c]);
    float4 v = *p;
    v.x *= f; v.y *= f; v.z *= f; v.w *= f;
    *p = v;
}

// ------------------------------------------------------------------
extern "C" void kernel_launch(void* const* d_in, const int* in_sizes, int n_in,
                              void* d_out, int out_size) {
    (void)in_sizes; (void)n_in; (void)out_size;
    const float* x = (const float*)d_in[0];       // (4,512,32,32)
    const float* anchor = (const float*)d_in[1];  // (64,512)
    const float* sp = (const float*)d_in[2];      // (64,512)
    float* out = (float*)d_out;
    float* nodes_out = out;                        // B*K*C (viewed (B,C,K))
    float* soft_out = out + (size_t)BB * KK * CC;  // B*K*N

    k1_prep<<<KK, 256>>>(anchor, sp);
    k2_d2_softmax<<<dim3(NN / 32, BB), 128>>>(x, soft_out);
    k3_num<<<dim3(CC / 64, BB, 4), 256>>>(soft_out, x);
    k4_nodes<<<dim3(KK, BB), 128>>>(anchor, nodes_out);
    k5_scale<<<dim3(KK, BB), 128>>>(nodes_out);
}